// round 1
// baseline (speedup 1.0000x reference)
#include <cuda_runtime.h>
#include <math.h>

#define N_NODES 50000
#define N_EDGES 1600000
#define NH      72
#define NF1     146     // 2*72+2
#define NFH     152     // 72+72+8
#define BN_EPS  1e-5f

// ---------------- device scratch (static allocation, allowed) ----------------
__device__ float g_agg_h[N_NODES * NH];   // segment_sum(m) per node
__device__ float g_agg_x[N_NODES * 4];    // segment_sum(trans)
__device__ float g_cnt[N_NODES];          // edge counts per node
__device__ float g_zh[N_NODES * NH];      // node-MLP pre-BN activations
__device__ float g_esum[NH], g_esq[NH], g_escale[NH], g_eshift[NH];
__device__ float g_hsum[NH], g_hsq[NH], g_hscale[NH], g_hshift[NH];

__device__ __forceinline__ float psi_f(float p) {
    return copysignf(log1pf(fabsf(p)), p);
}

// ---------------- K0: zero accumulators ----------------
__global__ void k0_zero() {
    int idx = blockIdx.x * blockDim.x + threadIdx.x;
    int stride = gridDim.x * blockDim.x;
    for (int t = idx; t < N_NODES * NH; t += stride) g_agg_h[t] = 0.f;
    for (int t = idx; t < N_NODES * 4;  t += stride) g_agg_x[t] = 0.f;
    for (int t = idx; t < N_NODES;      t += stride) g_cnt[t]  = 0.f;
    if (idx < NH) { g_esum[idx] = 0.f; g_esq[idx] = 0.f; g_hsum[idx] = 0.f; g_hsq[idx] = 0.f; }
}

// ---------------- K1: edge pass 1 — z = feat@We1, BN stats ----------------
// block = 128 threads, 64 edges/block. thread = (edge, half), 36 channels each.
__global__ void k1_edge1(const float* __restrict__ h, const float* __restrict__ x,
                         const int* __restrict__ ei, const int* __restrict__ ej,
                         const float* __restrict__ We1, float* __restrict__ zbuf) {
    extern __shared__ float sm[];
    float* sW = sm;                 // NF1*NH = 10512
    float* sF = sm + NF1 * NH;      // 64 * 148

    const int tid = threadIdx.x;
    for (int t = tid; t < NF1 * NH; t += 128) sW[t] = We1[t];

    const int warp = tid >> 5, lane = tid & 31;
    const int ebase = blockIdx.x * 64;
    for (int t = 0; t < 16; ++t) {
        int le = warp * 16 + t;
        int ge = ebase + le;
        int i = ei[ge], j = ej[ge];
        float* f = sF + le * 148;
        f[lane]       = h[(size_t)i * NH + lane];
        f[32 + lane]  = h[(size_t)i * NH + 32 + lane];
        f[72 + lane]  = h[(size_t)j * NH + lane];
        f[104 + lane] = h[(size_t)j * NH + 32 + lane];
        if (lane < 8) {
            f[64 + lane]  = h[(size_t)i * NH + 64 + lane];
            f[136 + lane] = h[(size_t)j * NH + 64 + lane];
        }
        if (lane == 0) {
            float4 xi = *(const float4*)(x + 4 * (size_t)i);
            float4 xj = *(const float4*)(x + 4 * (size_t)j);
            float dx0 = xi.x - xj.x, dx1 = xi.y - xj.y, dx2 = xi.z - xj.z, dx3 = xi.w - xj.w;
            float nsq = dx0 * dx0 - dx1 * dx1 - dx2 * dx2 - dx3 * dx3;
            float dsq = xi.x * xj.x - xi.y * xj.y - xi.z * xj.z - xi.w * xj.w;
            f[144] = psi_f(nsq);
            f[145] = psi_f(dsq);
        }
    }
    __syncthreads();

    const int e = tid >> 1, half = tid & 1, c0 = half * 36;
    float acc[36];
#pragma unroll
    for (int c = 0; c < 36; ++c) acc[c] = 0.f;

    const float* fe = sF + e * 148;
#pragma unroll 2
    for (int k = 0; k < NF1; ++k) {
        float f = fe[k];
        const float4* wr = (const float4*)(sW + k * NH + c0);
#pragma unroll
        for (int c4 = 0; c4 < 9; ++c4) {
            float4 w = wr[c4];
            acc[c4 * 4 + 0] += f * w.x;
            acc[c4 * 4 + 1] += f * w.y;
            acc[c4 * 4 + 2] += f * w.z;
            acc[c4 * 4 + 3] += f * w.w;
        }
    }

    // BN stats: reduce across 16 edges within warp (lanes sharing `half`)
#pragma unroll
    for (int c = 0; c < 36; ++c) {
        float s = acc[c];
        float q = acc[c] * acc[c];
#pragma unroll
        for (int msk = 2; msk <= 16; msk <<= 1) {
            s += __shfl_xor_sync(0xffffffffu, s, msk);
            q += __shfl_xor_sync(0xffffffffu, q, msk);
        }
        if ((lane >> 1) == 0) {
            atomicAdd(&g_esum[c0 + c], s);
            atomicAdd(&g_esq[c0 + c], q);
        }
    }

    float* zr = zbuf + (size_t)(ebase + e) * NH + c0;
#pragma unroll
    for (int c4 = 0; c4 < 9; ++c4)
        ((float4*)zr)[c4] = make_float4(acc[c4 * 4], acc[c4 * 4 + 1], acc[c4 * 4 + 2], acc[c4 * 4 + 3]);
}

// ---------------- BN finalize (which: 0=edge, 1=node) ----------------
__global__ void kbn_finalize(const float* __restrict__ gamma, const float* __restrict__ beta,
                             float invM, int which) {
    int c = threadIdx.x;
    if (c >= NH) return;
    float s_, q_;
    if (which == 0) { s_ = g_esum[c]; q_ = g_esq[c]; }
    else            { s_ = g_hsum[c]; q_ = g_hsq[c]; }
    float mu  = s_ * invM;
    float var = q_ * invM - mu * mu;
    float sc  = gamma[c] * rsqrtf(var + BN_EPS);
    if (which == 0) { g_escale[c] = sc; g_eshift[c] = beta[c] - mu * sc; }
    else            { g_hscale[c] = sc; g_hshift[c] = beta[c] - mu * sc; }
}

// ---------------- K2: edge pass 2 ----------------
__global__ void k2_edge2(const float* __restrict__ x,
                         const int* __restrict__ ei, const int* __restrict__ ej,
                         const float* __restrict__ We2, const float* __restrict__ be2,
                         const float* __restrict__ Wm,  const float* __restrict__ bm,
                         const float* __restrict__ Wx1, const float* __restrict__ bx1,
                         const float* __restrict__ Wx2,
                         float* __restrict__ mout /* z in, m out */) {
    extern __shared__ float sm[];
    float* sW2  = sm;                  // 5184
    float* sWx1 = sW2 + NH * NH;       // 5184
    float* sA   = sWx1 + NH * NH;      // 64*76
    float* sWm  = sA + 64 * 76;
    float* sWx2 = sWm + NH;
    float* sbe2 = sWx2 + NH;
    float* sbx1 = sbe2 + NH;
    float* sSc  = sbx1 + NH;
    float* sSh  = sSc + NH;

    const int tid = threadIdx.x;
    for (int t = tid; t < NH * NH; t += 128) { sW2[t] = We2[t]; sWx1[t] = Wx1[t]; }
    if (tid < NH) {
        sWm[tid]  = Wm[tid];  sWx2[tid] = Wx2[tid];
        sbe2[tid] = be2[tid]; sbx1[tid] = bx1[tid];
        sSc[tid]  = g_escale[tid]; sSh[tid] = g_eshift[tid];
    }
    __syncthreads();

    const int e = tid >> 1, half = tid & 1, c0 = half * 36;
    const int ge = blockIdx.x * 64 + e;

    // z -> BN -> ReLU -> sA
    {
        const float* zr = mout + (size_t)ge * NH + c0;
#pragma unroll
        for (int c4 = 0; c4 < 9; ++c4) {
            float4 z = ((const float4*)zr)[c4];
            int c = c0 + c4 * 4;
            sA[e * 76 + c + 0] = fmaxf(z.x * sSc[c + 0] + sSh[c + 0], 0.f);
            sA[e * 76 + c + 1] = fmaxf(z.y * sSc[c + 1] + sSh[c + 1], 0.f);
            sA[e * 76 + c + 2] = fmaxf(z.z * sSc[c + 2] + sSh[c + 2], 0.f);
            sA[e * 76 + c + 3] = fmaxf(z.w * sSc[c + 3] + sSh[c + 3], 0.f);
        }
    }
    __syncthreads();

    // e = relu(a @ We2 + be2)
    float acc[36];
#pragma unroll
    for (int c = 0; c < 36; ++c) acc[c] = 0.f;
    const float* ae = sA + e * 76;
#pragma unroll 2
    for (int k = 0; k < NH; ++k) {
        float f = ae[k];
        const float4* wr = (const float4*)(sW2 + k * NH + c0);
#pragma unroll
        for (int c4 = 0; c4 < 9; ++c4) {
            float4 w = wr[c4];
            acc[c4 * 4 + 0] += f * w.x;
            acc[c4 * 4 + 1] += f * w.y;
            acc[c4 * 4 + 2] += f * w.z;
            acc[c4 * 4 + 3] += f * w.w;
        }
    }
    float pd = 0.f;
#pragma unroll
    for (int c = 0; c < 36; ++c) {
        float v = fmaxf(acc[c] + sbe2[c0 + c], 0.f);
        acc[c] = v;
        pd += v * sWm[c0 + c];
    }
    pd += __shfl_xor_sync(0xffffffffu, pd, 1);
    float w = 1.f / (1.f + expf(-(pd + bm[0])));

    __syncthreads();  // all reads of sA (a) complete before overwriting with m

    const int i = ei[ge];
    float* mr = mout + (size_t)ge * NH + c0;
#pragma unroll
    for (int c4 = 0; c4 < 9; ++c4) {
        float m0 = acc[c4 * 4 + 0] * w, m1 = acc[c4 * 4 + 1] * w;
        float m2 = acc[c4 * 4 + 2] * w, m3 = acc[c4 * 4 + 3] * w;
        ((float4*)mr)[c4] = make_float4(m0, m1, m2, m3);
        int c = c0 + c4 * 4;
        sA[e * 76 + c + 0] = m0; sA[e * 76 + c + 1] = m1;
        sA[e * 76 + c + 2] = m2; sA[e * 76 + c + 3] = m3;
        atomicAdd(&g_agg_h[(size_t)i * NH + c + 0], m0);
        atomicAdd(&g_agg_h[(size_t)i * NH + c + 1], m1);
        atomicAdd(&g_agg_h[(size_t)i * NH + c + 2], m2);
        atomicAdd(&g_agg_h[(size_t)i * NH + c + 3], m3);
    }
    __syncthreads();

    // px = relu(m @ Wx1 + bx1) @ Wx2
    float tac[36];
#pragma unroll
    for (int c = 0; c < 36; ++c) tac[c] = 0.f;
#pragma unroll 2
    for (int k = 0; k < NH; ++k) {
        float f = ae[k];
        const float4* wr = (const float4*)(sWx1 + k * NH + c0);
#pragma unroll
        for (int c4 = 0; c4 < 9; ++c4) {
            float4 w4 = wr[c4];
            tac[c4 * 4 + 0] += f * w4.x;
            tac[c4 * 4 + 1] += f * w4.y;
            tac[c4 * 4 + 2] += f * w4.z;
            tac[c4 * 4 + 3] += f * w4.w;
        }
    }
    float px = 0.f;
#pragma unroll
    for (int c = 0; c < 36; ++c)
        px += fmaxf(tac[c] + sbx1[c0 + c], 0.f) * sWx2[c0 + c];
    px += __shfl_xor_sync(0xffffffffu, px, 1);

    if (half == 0) {
        const int j = ej[ge];
        float4 xi = *(const float4*)(x + 4 * (size_t)i);
        float4 xj = *(const float4*)(x + 4 * (size_t)j);
        float t0 = fminf(fmaxf((xi.x - xj.x) * px, -100.f), 100.f);
        float t1 = fminf(fmaxf((xi.y - xj.y) * px, -100.f), 100.f);
        float t2 = fminf(fmaxf((xi.z - xj.z) * px, -100.f), 100.f);
        float t3 = fminf(fmaxf((xi.w - xj.w) * px, -100.f), 100.f);
        atomicAdd(&g_agg_x[(size_t)i * 4 + 0], t0);
        atomicAdd(&g_agg_x[(size_t)i * 4 + 1], t1);
        atomicAdd(&g_agg_x[(size_t)i * 4 + 2], t2);
        atomicAdd(&g_agg_x[(size_t)i * 4 + 3], t3);
        atomicAdd(&g_cnt[i], 1.f);
    }
}

// ---------------- K3a: node pass 1 — zh = hcat@Wh1 + bh1, BN stats ----------------
__global__ void k3a_node1(const float* __restrict__ h, const float* __restrict__ nattr,
                          const float* __restrict__ Wh1, const float* __restrict__ bh1) {
    extern __shared__ float sm[];
    float* sW = sm;                  // NFH*NH = 10944
    float* sF = sW + NFH * NH;       // 64*154
    float* sB = sF + 64 * 154;       // 72

    const int tid = threadIdx.x;
    for (int t = tid; t < NFH * NH; t += 128) sW[t] = Wh1[t];
    if (tid < NH) sB[tid] = bh1[tid];

    const int warp = tid >> 5, lane = tid & 31;
    const int nbase = blockIdx.x * 64;
    for (int t = 0; t < 16; ++t) {
        int ln = warp * 16 + t;
        int n = nbase + ln;
        float* f = sF + ln * 154;
        if (n < N_NODES) {
            f[lane]       = h[(size_t)n * NH + lane];
            f[32 + lane]  = h[(size_t)n * NH + 32 + lane];
            f[72 + lane]  = g_agg_h[(size_t)n * NH + lane];
            f[104 + lane] = g_agg_h[(size_t)n * NH + 32 + lane];
            if (lane < 8) {
                f[64 + lane]  = h[(size_t)n * NH + 64 + lane];
                f[136 + lane] = g_agg_h[(size_t)n * NH + 64 + lane];
                f[144 + lane] = nattr[(size_t)n * 8 + lane];
            }
        } else {
            f[lane] = 0.f; f[32 + lane] = 0.f; f[72 + lane] = 0.f; f[104 + lane] = 0.f;
            if (lane < 8) { f[64 + lane] = 0.f; f[136 + lane] = 0.f; f[144 + lane] = 0.f; }
        }
    }
    __syncthreads();

    const int r = tid >> 1, half = tid & 1, c0 = half * 36;
    const int n = nbase + r;
    const bool valid = (n < N_NODES);

    float acc[36];
#pragma unroll
    for (int c = 0; c < 36; ++c) acc[c] = sB[c0 + c];

    const float* fe = sF + r * 154;
#pragma unroll 2
    for (int k = 0; k < NFH; ++k) {
        float f = fe[k];
        const float4* wr = (const float4*)(sW + k * NH + c0);
#pragma unroll
        for (int c4 = 0; c4 < 9; ++c4) {
            float4 w = wr[c4];
            acc[c4 * 4 + 0] += f * w.x;
            acc[c4 * 4 + 1] += f * w.y;
            acc[c4 * 4 + 2] += f * w.z;
            acc[c4 * 4 + 3] += f * w.w;
        }
    }

#pragma unroll
    for (int c = 0; c < 36; ++c) {
        float s = valid ? acc[c] : 0.f;
        float q = s * s;
#pragma unroll
        for (int msk = 2; msk <= 16; msk <<= 1) {
            s += __shfl_xor_sync(0xffffffffu, s, msk);
            q += __shfl_xor_sync(0xffffffffu, q, msk);
        }
        if ((lane >> 1) == 0) {
            atomicAdd(&g_hsum[c0 + c], s);
            atomicAdd(&g_hsq[c0 + c], q);
        }
    }

    if (valid) {
        float* zr = g_zh + (size_t)n * NH + c0;
#pragma unroll
        for (int c4 = 0; c4 < 9; ++c4)
            ((float4*)zr)[c4] = make_float4(acc[c4 * 4], acc[c4 * 4 + 1], acc[c4 * 4 + 2], acc[c4 * 4 + 3]);
    }
}

// ---------------- K3c: node pass 2 — h_out, x_out ----------------
__global__ void k3c_node2(const float* __restrict__ h, const float* __restrict__ x,
                          const float* __restrict__ Wh2, const float* __restrict__ bh2,
                          float* __restrict__ hout, float* __restrict__ xout) {
    extern __shared__ float sm[];
    float* sW  = sm;                 // 5184
    float* sA  = sW + NH * NH;       // 64*76
    float* sb  = sA + 64 * 76;
    float* sSc = sb + NH;
    float* sSh = sSc + NH;

    const int tid = threadIdx.x;
    for (int t = tid; t < NH * NH; t += 128) sW[t] = Wh2[t];
    if (tid < NH) { sb[tid] = bh2[tid]; sSc[tid] = g_hscale[tid]; sSh[tid] = g_hshift[tid]; }
    __syncthreads();

    const int r = tid >> 1, half = tid & 1, c0 = half * 36;
    const int n = blockIdx.x * 64 + r;
    const bool valid = (n < N_NODES);

    if (valid) {
        const float* zr = g_zh + (size_t)n * NH + c0;
#pragma unroll
        for (int c4 = 0; c4 < 9; ++c4) {
            float4 z = ((const float4*)zr)[c4];
            int c = c0 + c4 * 4;
            sA[r * 76 + c + 0] = fmaxf(z.x * sSc[c + 0] + sSh[c + 0], 0.f);
            sA[r * 76 + c + 1] = fmaxf(z.y * sSc[c + 1] + sSh[c + 1], 0.f);
            sA[r * 76 + c + 2] = fmaxf(z.z * sSc[c + 2] + sSh[c + 2], 0.f);
            sA[r * 76 + c + 3] = fmaxf(z.w * sSc[c + 3] + sSh[c + 3], 0.f);
        }
    } else {
#pragma unroll
        for (int c4 = 0; c4 < 9; ++c4) {
            int c = c0 + c4 * 4;
            sA[r * 76 + c + 0] = 0.f; sA[r * 76 + c + 1] = 0.f;
            sA[r * 76 + c + 2] = 0.f; sA[r * 76 + c + 3] = 0.f;
        }
    }
    __syncthreads();

    float acc[36];
#pragma unroll
    for (int c = 0; c < 36; ++c) acc[c] = 0.f;
    const float* ae = sA + r * 76;
#pragma unroll 2
    for (int k = 0; k < NH; ++k) {
        float f = ae[k];
        const float4* wr = (const float4*)(sW + k * NH + c0);
#pragma unroll
        for (int c4 = 0; c4 < 9; ++c4) {
            float4 w = wr[c4];
            acc[c4 * 4 + 0] += f * w.x;
            acc[c4 * 4 + 1] += f * w.y;
            acc[c4 * 4 + 2] += f * w.z;
            acc[c4 * 4 + 3] += f * w.w;
        }
    }

    if (valid) {
        const float* hr = h + (size_t)n * NH + c0;
        float* orow = hout + (size_t)n * NH + c0;
#pragma unroll
        for (int c4 = 0; c4 < 9; ++c4) {
            float4 hv = ((const float4*)hr)[c4];
            int c = c0 + c4 * 4;
            ((float4*)orow)[c4] = make_float4(hv.x + acc[c + 0 - c0] + sb[c + 0],
                                              hv.y + acc[c + 1 - c0] + sb[c + 1],
                                              hv.z + acc[c + 2 - c0] + sb[c + 2],
                                              hv.w + acc[c + 3 - c0] + sb[c + 3]);
        }
        if (half == 0) {
            float4 xi = *(const float4*)(x + 4 * (size_t)n);
            float4 ax = *(const float4*)(g_agg_x + 4 * (size_t)n);
            float inv = 1.f / fmaxf(g_cnt[n], 1.f);
            *(float4*)(xout + 4 * (size_t)n) =
                make_float4(xi.x + ax.x * inv, xi.y + ax.y * inv,
                            xi.z + ax.z * inv, xi.w + ax.w * inv);
        }
    }
}

// ---------------- launch ----------------
extern "C" void kernel_launch(void* const* d_in, const int* in_sizes, int n_in,
                              void* d_out, int out_size) {
    const float* h      = (const float*)d_in[0];
    const float* x      = (const float*)d_in[1];
    const float* nattr  = (const float*)d_in[2];
    const int*   edges  = (const int*)d_in[3];
    const float* We1    = (const float*)d_in[4];
    const float* bn_e_g = (const float*)d_in[5];
    const float* bn_e_b = (const float*)d_in[6];
    const float* We2    = (const float*)d_in[7];
    const float* be2    = (const float*)d_in[8];
    const float* Wh1    = (const float*)d_in[9];
    const float* bh1    = (const float*)d_in[10];
    const float* bn_h_g = (const float*)d_in[11];
    const float* bn_h_b = (const float*)d_in[12];
    const float* Wh2    = (const float*)d_in[13];
    const float* bh2    = (const float*)d_in[14];
    const float* Wx1    = (const float*)d_in[15];
    const float* bx1    = (const float*)d_in[16];
    const float* Wx2    = (const float*)d_in[17];
    const float* Wm     = (const float*)d_in[18];
    const float* bm     = (const float*)d_in[19];

    const int* ei = edges;
    const int* ej = edges + N_EDGES;

    float* out  = (float*)d_out;
    float* hout = out;
    float* xout = out + (size_t)N_NODES * NH;
    float* mout = xout + (size_t)N_NODES * 4;   // E*NH; also used as z scratch

    int smem1  = (NF1 * NH + 64 * 148) * 4;
    int smem2  = (NH * NH * 2 + 64 * 76 + 6 * NH) * 4;
    int smem3a = (NFH * NH + 64 * 154 + NH) * 4;
    int smem3c = (NH * NH + 64 * 76 + 3 * NH) * 4;

    cudaFuncSetAttribute(k1_edge1,  cudaFuncAttributeMaxDynamicSharedMemorySize, smem1);
    cudaFuncSetAttribute(k2_edge2,  cudaFuncAttributeMaxDynamicSharedMemorySize, smem2);
    cudaFuncSetAttribute(k3a_node1, cudaFuncAttributeMaxDynamicSharedMemorySize, smem3a);
    cudaFuncSetAttribute(k3c_node2, cudaFuncAttributeMaxDynamicSharedMemorySize, smem3c);

    k0_zero<<<2048, 256>>>();
    k1_edge1<<<N_EDGES / 64, 128, smem1>>>(h, x, ei, ej, We1, mout);
    kbn_finalize<<<1, 128>>>(bn_e_g, bn_e_b, 1.f / (float)N_EDGES, 0);
    k2_edge2<<<N_EDGES / 64, 128, smem2>>>(x, ei, ej, We2, be2, Wm, bm, Wx1, bx1, Wx2, mout);
    k3a_node1<<<(N_NODES + 63) / 64, 128, smem3a>>>(h, nattr, Wh1, bh1);
    kbn_finalize<<<1, 128>>>(bn_h_g, bn_h_b, 1.f / (float)N_NODES, 1);
    k3c_node2<<<(N_NODES + 63) / 64, 128, smem3c>>>(h, x, Wh2, bh2, hout, xout);
}

// round 2
// speedup vs baseline: 1.0688x; 1.0688x over previous
#include <cuda_runtime.h>
#include <math.h>

#define N_NODES 50000
#define N_EDGES 1600000
#define NH      72
#define NF1     146     // 2*72+2
#define NFH     152     // 72+72+8
#define BN_EPS  1e-5f
#define SF1     149     // padded feature row stride (k1)
#define SA2     77      // padded activation row stride (k2/k3c)
#define SF3     154     // feature row stride (k3a) — conflict-free already

typedef unsigned long long u64;

// ---------------- device scratch ----------------
__device__ __align__(16) float g_agg_h[N_NODES * NH];
__device__ __align__(16) float g_agg_x[N_NODES * 4];
__device__ float g_cnt[N_NODES];
__device__ __align__(16) float g_zh[N_NODES * NH];
__device__ float g_esum[NH], g_esq[NH], g_escale[NH], g_eshift[NH];
__device__ float g_hsum[NH], g_hsq[NH], g_hscale[NH], g_hshift[NH];

__device__ __forceinline__ float psi_f(float p) {
    return copysignf(log1pf(fabsf(p)), p);
}
__device__ __forceinline__ u64 pack2(float f) {
    u64 r; asm("mov.b64 %0, {%1, %1};" : "=l"(r) : "f"(f)); return r;
}
__device__ __forceinline__ void ffma2(u64& d, u64 a, u64 b) {
    asm("fma.rn.f32x2 %0, %1, %2, %0;" : "+l"(d) : "l"(a), "l"(b));
}
__device__ __forceinline__ float2 unpack2(u64 v) {
    float2 r; asm("mov.b64 {%0, %1}, %2;" : "=f"(r.x), "=f"(r.y) : "l"(v)); return r;
}

// ---------------- K0: zero accumulators ----------------
__global__ void k0_zero() {
    int idx = blockIdx.x * blockDim.x + threadIdx.x;
    int stride = gridDim.x * blockDim.x;
    for (int t = idx; t < N_NODES * NH; t += stride) g_agg_h[t] = 0.f;
    for (int t = idx; t < N_NODES * 4;  t += stride) g_agg_x[t] = 0.f;
    for (int t = idx; t < N_NODES;      t += stride) g_cnt[t]  = 0.f;
    if (idx < NH) { g_esum[idx] = 0.f; g_esq[idx] = 0.f; g_hsum[idx] = 0.f; g_hsq[idx] = 0.f; }
}

// ---------------- K1: edge pass 1 — z = feat@We1, BN stats ----------------
__global__ void k1_edge1(const float* __restrict__ h, const float* __restrict__ x,
                         const int* __restrict__ ei, const int* __restrict__ ej,
                         const float* __restrict__ We1, float* __restrict__ zbuf) {
    extern __shared__ float sm[];
    float* sW = sm;                 // NF1*NH
    float* sF = sm + NF1 * NH;      // 64 * SF1

    const int tid = threadIdx.x;
    for (int t = tid; t < NF1 * NH; t += 128) sW[t] = We1[t];

    const int warp = tid >> 5, lane = tid & 31;
    const int ebase = blockIdx.x * 64;
    for (int t = 0; t < 16; ++t) {
        int le = warp * 16 + t;
        int ge = ebase + le;
        int i = ei[ge], j = ej[ge];
        float* f = sF + le * SF1;
        f[lane]       = h[(size_t)i * NH + lane];
        f[32 + lane]  = h[(size_t)i * NH + 32 + lane];
        f[72 + lane]  = h[(size_t)j * NH + lane];
        f[104 + lane] = h[(size_t)j * NH + 32 + lane];
        if (lane < 8) {
            f[64 + lane]  = h[(size_t)i * NH + 64 + lane];
            f[136 + lane] = h[(size_t)j * NH + 64 + lane];
        }
        if (lane == 0) {
            float4 xi = *(const float4*)(x + 4 * (size_t)i);
            float4 xj = *(const float4*)(x + 4 * (size_t)j);
            float dx0 = xi.x - xj.x, dx1 = xi.y - xj.y, dx2 = xi.z - xj.z, dx3 = xi.w - xj.w;
            float nsq = dx0 * dx0 - dx1 * dx1 - dx2 * dx2 - dx3 * dx3;
            float dsq = xi.x * xj.x - xi.y * xj.y - xi.z * xj.z - xi.w * xj.w;
            f[144] = psi_f(nsq);
            f[145] = psi_f(dsq);
        }
    }
    __syncthreads();

    const int e = tid >> 1, half = tid & 1, c0 = half * 36;
    u64 acc[18];
#pragma unroll
    for (int c = 0; c < 18; ++c) acc[c] = 0ull;

    const float* fe = sF + e * SF1;
#pragma unroll 2
    for (int k = 0; k < NF1; ++k) {
        u64 f2 = pack2(fe[k]);
        const ulonglong2* wr = (const ulonglong2*)(sW + k * NH + c0);
#pragma unroll
        for (int c2 = 0; c2 < 9; ++c2) {
            ulonglong2 w = wr[c2];
            ffma2(acc[2 * c2],     w.x, f2);
            ffma2(acc[2 * c2 + 1], w.y, f2);
        }
    }

    // store z (packed pairs are already in memory order)
    {
        ulonglong2* zr = (ulonglong2*)(zbuf + (size_t)(ebase + e) * NH + c0);
#pragma unroll
        for (int c2 = 0; c2 < 9; ++c2) {
            ulonglong2 o; o.x = acc[2 * c2]; o.y = acc[2 * c2 + 1];
            zr[c2] = o;
        }
    }

    // BN stats
    float a36[36];
#pragma unroll
    for (int c2 = 0; c2 < 18; ++c2) {
        float2 v = unpack2(acc[c2]);
        a36[2 * c2] = v.x; a36[2 * c2 + 1] = v.y;
    }
#pragma unroll
    for (int c = 0; c < 36; ++c) {
        float s = a36[c];
        float q = s * s;
#pragma unroll
        for (int msk = 2; msk <= 16; msk <<= 1) {
            s += __shfl_xor_sync(0xffffffffu, s, msk);
            q += __shfl_xor_sync(0xffffffffu, q, msk);
        }
        if ((lane >> 1) == 0) {
            atomicAdd(&g_esum[c0 + c], s);
            atomicAdd(&g_esq[c0 + c], q);
        }
    }
}

// ---------------- BN finalize ----------------
__global__ void kbn_finalize(const float* __restrict__ gamma, const float* __restrict__ beta,
                             float invM, int which) {
    int c = threadIdx.x;
    if (c >= NH) return;
    float s_, q_;
    if (which == 0) { s_ = g_esum[c]; q_ = g_esq[c]; }
    else            { s_ = g_hsum[c]; q_ = g_hsq[c]; }
    float mu  = s_ * invM;
    float var = q_ * invM - mu * mu;
    float sc  = gamma[c] * rsqrtf(var + BN_EPS);
    if (which == 0) { g_escale[c] = sc; g_eshift[c] = beta[c] - mu * sc; }
    else            { g_hscale[c] = sc; g_hshift[c] = beta[c] - mu * sc; }
}

// ---------------- K2: edge pass 2 ----------------
__global__ void k2_edge2(const float* __restrict__ x,
                         const int* __restrict__ ei, const int* __restrict__ ej,
                         const float* __restrict__ We2, const float* __restrict__ be2,
                         const float* __restrict__ Wm,  const float* __restrict__ bm,
                         const float* __restrict__ Wx1, const float* __restrict__ bx1,
                         const float* __restrict__ Wx2,
                         float* __restrict__ mout /* z in, m out */) {
    extern __shared__ float sm[];
    float* sW2  = sm;                   // NH*NH
    float* sWx1 = sW2 + NH * NH;        // NH*NH
    float* sA   = sWx1 + NH * NH;       // 64 * SA2
    float* sWm  = sA + 64 * SA2;
    float* sWx2 = sWm + NH;
    float* sbe2 = sWx2 + NH;
    float* sbx1 = sbe2 + NH;
    float* sSc  = sbx1 + NH;
    float* sSh  = sSc + NH;

    const int tid = threadIdx.x;
    for (int t = tid; t < NH * NH; t += 128) { sW2[t] = We2[t]; sWx1[t] = Wx1[t]; }
    if (tid < NH) {
        sWm[tid]  = Wm[tid];  sWx2[tid] = Wx2[tid];
        sbe2[tid] = be2[tid]; sbx1[tid] = bx1[tid];
        sSc[tid]  = g_escale[tid]; sSh[tid] = g_eshift[tid];
    }
    __syncthreads();

    const int e = tid >> 1, half = tid & 1, c0 = half * 36;
    const int ge = blockIdx.x * 64 + e;

    // z -> BN -> ReLU -> sA (each row touched only by its own lane pair)
    {
        const float* zr = mout + (size_t)ge * NH + c0;
#pragma unroll
        for (int c4 = 0; c4 < 9; ++c4) {
            float4 z = ((const float4*)zr)[c4];
            int c = c0 + c4 * 4;
            sA[e * SA2 + c + 0] = fmaxf(z.x * sSc[c + 0] + sSh[c + 0], 0.f);
            sA[e * SA2 + c + 1] = fmaxf(z.y * sSc[c + 1] + sSh[c + 1], 0.f);
            sA[e * SA2 + c + 2] = fmaxf(z.z * sSc[c + 2] + sSh[c + 2], 0.f);
            sA[e * SA2 + c + 3] = fmaxf(z.w * sSc[c + 3] + sSh[c + 3], 0.f);
        }
    }
    __syncwarp();

    // e_act = relu(a @ We2 + be2)
    u64 acc[18];
#pragma unroll
    for (int c = 0; c < 18; ++c) acc[c] = 0ull;
    const float* ae = sA + e * SA2;
#pragma unroll 2
    for (int k = 0; k < NH; ++k) {
        u64 f2 = pack2(ae[k]);
        const ulonglong2* wr = (const ulonglong2*)(sW2 + k * NH + c0);
#pragma unroll
        for (int c2 = 0; c2 < 9; ++c2) {
            ulonglong2 w = wr[c2];
            ffma2(acc[2 * c2],     w.x, f2);
            ffma2(acc[2 * c2 + 1], w.y, f2);
        }
    }
    float m36[36];
    float pd = 0.f;
#pragma unroll
    for (int c2 = 0; c2 < 18; ++c2) {
        float2 v = unpack2(acc[c2]);
        float v0 = fmaxf(v.x + sbe2[c0 + 2 * c2], 0.f);
        float v1 = fmaxf(v.y + sbe2[c0 + 2 * c2 + 1], 0.f);
        m36[2 * c2] = v0; m36[2 * c2 + 1] = v1;
        pd += v0 * sWm[c0 + 2 * c2] + v1 * sWm[c0 + 2 * c2 + 1];
    }
    pd += __shfl_xor_sync(0xffffffffu, pd, 1);
    float w = 1.f / (1.f + expf(-(pd + bm[0])));

    __syncwarp();   // both halves done reading a-row before overwrite with m

    const int i = ei[ge];
    float* mr = mout + (size_t)ge * NH + c0;
#pragma unroll
    for (int c4 = 0; c4 < 9; ++c4) {
        float m0 = m36[c4 * 4 + 0] * w, m1 = m36[c4 * 4 + 1] * w;
        float m2 = m36[c4 * 4 + 2] * w, m3 = m36[c4 * 4 + 3] * w;
        ((float4*)mr)[c4] = make_float4(m0, m1, m2, m3);
        int c = c0 + c4 * 4;
        sA[e * SA2 + c + 0] = m0; sA[e * SA2 + c + 1] = m1;
        sA[e * SA2 + c + 2] = m2; sA[e * SA2 + c + 3] = m3;
        atomicAdd((float4*)&g_agg_h[(size_t)i * NH + c], make_float4(m0, m1, m2, m3));
    }
    __syncwarp();

    // px = relu(m @ Wx1 + bx1) @ Wx2
    u64 tac[18];
#pragma unroll
    for (int c = 0; c < 18; ++c) tac[c] = 0ull;
#pragma unroll 2
    for (int k = 0; k < NH; ++k) {
        u64 f2 = pack2(ae[k]);
        const ulonglong2* wr = (const ulonglong2*)(sWx1 + k * NH + c0);
#pragma unroll
        for (int c2 = 0; c2 < 9; ++c2) {
            ulonglong2 w4 = wr[c2];
            ffma2(tac[2 * c2],     w4.x, f2);
            ffma2(tac[2 * c2 + 1], w4.y, f2);
        }
    }
    float px = 0.f;
#pragma unroll
    for (int c2 = 0; c2 < 18; ++c2) {
        float2 v = unpack2(tac[c2]);
        px += fmaxf(v.x + sbx1[c0 + 2 * c2], 0.f) * sWx2[c0 + 2 * c2];
        px += fmaxf(v.y + sbx1[c0 + 2 * c2 + 1], 0.f) * sWx2[c0 + 2 * c2 + 1];
    }
    px += __shfl_xor_sync(0xffffffffu, px, 1);

    if (half == 0) {
        const int j = ej[ge];
        float4 xi = *(const float4*)(x + 4 * (size_t)i);
        float4 xj = *(const float4*)(x + 4 * (size_t)j);
        float t0 = fminf(fmaxf((xi.x - xj.x) * px, -100.f), 100.f);
        float t1 = fminf(fmaxf((xi.y - xj.y) * px, -100.f), 100.f);
        float t2 = fminf(fmaxf((xi.z - xj.z) * px, -100.f), 100.f);
        float t3 = fminf(fmaxf((xi.w - xj.w) * px, -100.f), 100.f);
        atomicAdd((float4*)&g_agg_x[(size_t)i * 4], make_float4(t0, t1, t2, t3));
        atomicAdd(&g_cnt[i], 1.f);
    }
}

// ---------------- K3a: node pass 1 ----------------
__global__ void k3a_node1(const float* __restrict__ h, const float* __restrict__ nattr,
                          const float* __restrict__ Wh1, const float* __restrict__ bh1) {
    extern __shared__ float sm[];
    float* sW = sm;                  // NFH*NH
    float* sF = sW + NFH * NH;       // 64*SF3
    float* sB = sF + 64 * SF3;       // NH

    const int tid = threadIdx.x;
    for (int t = tid; t < NFH * NH; t += 128) sW[t] = Wh1[t];
    if (tid < NH) sB[tid] = bh1[tid];

    const int warp = tid >> 5, lane = tid & 31;
    const int nbase = blockIdx.x * 64;
    for (int t = 0; t < 16; ++t) {
        int ln = warp * 16 + t;
        int n = nbase + ln;
        float* f = sF + ln * SF3;
        if (n < N_NODES) {
            f[lane]       = h[(size_t)n * NH + lane];
            f[32 + lane]  = h[(size_t)n * NH + 32 + lane];
            f[72 + lane]  = g_agg_h[(size_t)n * NH + lane];
            f[104 + lane] = g_agg_h[(size_t)n * NH + 32 + lane];
            if (lane < 8) {
                f[64 + lane]  = h[(size_t)n * NH + 64 + lane];
                f[136 + lane] = g_agg_h[(size_t)n * NH + 64 + lane];
                f[144 + lane] = nattr[(size_t)n * 8 + lane];
            }
        } else {
            f[lane] = 0.f; f[32 + lane] = 0.f; f[72 + lane] = 0.f; f[104 + lane] = 0.f;
            if (lane < 8) { f[64 + lane] = 0.f; f[136 + lane] = 0.f; f[144 + lane] = 0.f; }
        }
    }
    __syncthreads();

    const int r = tid >> 1, half = tid & 1, c0 = half * 36;
    const int n = nbase + r;
    const bool valid = (n < N_NODES);

    u64 acc[18];
    {
        const u64* bp = (const u64*)(sB + c0);
#pragma unroll
        for (int c2 = 0; c2 < 18; ++c2) acc[c2] = bp[c2];
    }
    const float* fe = sF + r * SF3;
#pragma unroll 2
    for (int k = 0; k < NFH; ++k) {
        u64 f2 = pack2(fe[k]);
        const ulonglong2* wr = (const ulonglong2*)(sW + k * NH + c0);
#pragma unroll
        for (int c2 = 0; c2 < 9; ++c2) {
            ulonglong2 w = wr[c2];
            ffma2(acc[2 * c2],     w.x, f2);
            ffma2(acc[2 * c2 + 1], w.y, f2);
        }
    }

    float a36[36];
#pragma unroll
    for (int c2 = 0; c2 < 18; ++c2) {
        float2 v = unpack2(acc[c2]);
        a36[2 * c2] = v.x; a36[2 * c2 + 1] = v.y;
    }
#pragma unroll
    for (int c = 0; c < 36; ++c) {
        float s = valid ? a36[c] : 0.f;
        float q = s * s;
#pragma unroll
        for (int msk = 2; msk <= 16; msk <<= 1) {
            s += __shfl_xor_sync(0xffffffffu, s, msk);
            q += __shfl_xor_sync(0xffffffffu, q, msk);
        }
        if ((lane >> 1) == 0) {
            atomicAdd(&g_hsum[c0 + c], s);
            atomicAdd(&g_hsq[c0 + c], q);
        }
    }

    if (valid) {
        ulonglong2* zr = (ulonglong2*)(g_zh + (size_t)n * NH + c0);
#pragma unroll
        for (int c2 = 0; c2 < 9; ++c2) {
            ulonglong2 o; o.x = acc[2 * c2]; o.y = acc[2 * c2 + 1];
            zr[c2] = o;
        }
    }
}

// ---------------- K3c: node pass 2 ----------------
__global__ void k3c_node2(const float* __restrict__ h, const float* __restrict__ x,
                          const float* __restrict__ Wh2, const float* __restrict__ bh2,
                          float* __restrict__ hout, float* __restrict__ xout) {
    extern __shared__ float sm[];
    float* sW  = sm;                 // NH*NH
    float* sA  = sW + NH * NH;       // 64*SA2
    float* sb  = sA + 64 * SA2;
    float* sSc = sb + NH;
    float* sSh = sSc + NH;

    const int tid = threadIdx.x;
    for (int t = tid; t < NH * NH; t += 128) sW[t] = Wh2[t];
    if (tid < NH) { sb[tid] = bh2[tid]; sSc[tid] = g_hscale[tid]; sSh[tid] = g_hshift[tid]; }
    __syncthreads();

    const int r = tid >> 1, half = tid & 1, c0 = half * 36;
    const int n = blockIdx.x * 64 + r;
    const bool valid = (n < N_NODES);

    if (valid) {
        const float* zr = g_zh + (size_t)n * NH + c0;
#pragma unroll
        for (int c4 = 0; c4 < 9; ++c4) {
            float4 z = ((const float4*)zr)[c4];
            int c = c0 + c4 * 4;
            sA[r * SA2 + c + 0] = fmaxf(z.x * sSc[c + 0] + sSh[c + 0], 0.f);
            sA[r * SA2 + c + 1] = fmaxf(z.y * sSc[c + 1] + sSh[c + 1], 0.f);
            sA[r * SA2 + c + 2] = fmaxf(z.z * sSc[c + 2] + sSh[c + 2], 0.f);
            sA[r * SA2 + c + 3] = fmaxf(z.w * sSc[c + 3] + sSh[c + 3], 0.f);
        }
    } else {
#pragma unroll
        for (int c4 = 0; c4 < 9; ++c4) {
            int c = c0 + c4 * 4;
            sA[r * SA2 + c + 0] = 0.f; sA[r * SA2 + c + 1] = 0.f;
            sA[r * SA2 + c + 2] = 0.f; sA[r * SA2 + c + 3] = 0.f;
        }
    }
    __syncwarp();

    u64 acc[18];
#pragma unroll
    for (int c = 0; c < 18; ++c) acc[c] = 0ull;
    const float* ae = sA + r * SA2;
#pragma unroll 2
    for (int k = 0; k < NH; ++k) {
        u64 f2 = pack2(ae[k]);
        const ulonglong2* wr = (const ulonglong2*)(sW + k * NH + c0);
#pragma unroll
        for (int c2 = 0; c2 < 9; ++c2) {
            ulonglong2 w = wr[c2];
            ffma2(acc[2 * c2],     w.x, f2);
            ffma2(acc[2 * c2 + 1], w.y, f2);
        }
    }

    if (valid) {
        const float* hr = h + (size_t)n * NH + c0;
        float* orow = hout + (size_t)n * NH + c0;
#pragma unroll
        for (int c4 = 0; c4 < 9; ++c4) {
            float2 v0 = unpack2(acc[2 * c4]);
            float2 v1 = unpack2(acc[2 * c4 + 1]);
            float4 hv = ((const float4*)hr)[c4];
            int c = c0 + c4 * 4;
            ((float4*)orow)[c4] = make_float4(hv.x + v0.x + sb[c + 0],
                                              hv.y + v0.y + sb[c + 1],
                                              hv.z + v1.x + sb[c + 2],
                                              hv.w + v1.y + sb[c + 3]);
        }
        if (half == 0) {
            float4 xi = *(const float4*)(x + 4 * (size_t)n);
            float4 ax = *(const float4*)(g_agg_x + 4 * (size_t)n);
            float inv = 1.f / fmaxf(g_cnt[n], 1.f);
            *(float4*)(xout + 4 * (size_t)n) =
                make_float4(xi.x + ax.x * inv, xi.y + ax.y * inv,
                            xi.z + ax.z * inv, xi.w + ax.w * inv);
        }
    }
}

// ---------------- launch ----------------
extern "C" void kernel_launch(void* const* d_in, const int* in_sizes, int n_in,
                              void* d_out, int out_size) {
    const float* h      = (const float*)d_in[0];
    const float* x      = (const float*)d_in[1];
    const float* nattr  = (const float*)d_in[2];
    const int*   edges  = (const int*)d_in[3];
    const float* We1    = (const float*)d_in[4];
    const float* bn_e_g = (const float*)d_in[5];
    const float* bn_e_b = (const float*)d_in[6];
    const float* We2    = (const float*)d_in[7];
    const float* be2    = (const float*)d_in[8];
    const float* Wh1    = (const float*)d_in[9];
    const float* bh1    = (const float*)d_in[10];
    const float* bn_h_g = (const float*)d_in[11];
    const float* bn_h_b = (const float*)d_in[12];
    const float* Wh2    = (const float*)d_in[13];
    const float* bh2    = (const float*)d_in[14];
    const float* Wx1    = (const float*)d_in[15];
    const float* bx1    = (const float*)d_in[16];
    const float* Wx2    = (const float*)d_in[17];
    const float* Wm     = (const float*)d_in[18];
    const float* bm     = (const float*)d_in[19];

    const int* ei = edges;
    const int* ej = edges + N_EDGES;

    float* out  = (float*)d_out;
    float* hout = out;
    float* xout = out + (size_t)N_NODES * NH;
    float* mout = xout + (size_t)N_NODES * 4;   // E*NH; also used as z scratch

    int smem1  = (NF1 * NH + 64 * SF1) * 4;
    int smem2  = (2 * NH * NH + 64 * SA2 + 6 * NH) * 4;
    int smem3a = (NFH * NH + 64 * SF3 + NH) * 4;
    int smem3c = (NH * NH + 64 * SA2 + 3 * NH) * 4;

    cudaFuncSetAttribute(k1_edge1,  cudaFuncAttributeMaxDynamicSharedMemorySize, smem1);
    cudaFuncSetAttribute(k2_edge2,  cudaFuncAttributeMaxDynamicSharedMemorySize, smem2);
    cudaFuncSetAttribute(k3a_node1, cudaFuncAttributeMaxDynamicSharedMemorySize, smem3a);
    cudaFuncSetAttribute(k3c_node2, cudaFuncAttributeMaxDynamicSharedMemorySize, smem3c);

    k0_zero<<<2048, 256>>>();
    k1_edge1<<<N_EDGES / 64, 128, smem1>>>(h, x, ei, ej, We1, mout);
    kbn_finalize<<<1, 128>>>(bn_e_g, bn_e_b, 1.f / (float)N_EDGES, 0);
    k2_edge2<<<N_EDGES / 64, 128, smem2>>>(x, ei, ej, We2, be2, Wm, bm, Wx1, bx1, Wx2, mout);
    k3a_node1<<<(N_NODES + 63) / 64, 128, smem3a>>>(h, nattr, Wh1, bh1);
    kbn_finalize<<<1, 128>>>(bn_h_g, bn_h_b, 1.f / (float)N_NODES, 1);
    k3c_node2<<<(N_NODES + 63) / 64, 128, smem3c>>>(h, x, Wh2, bh2, hout, xout);
}